// round 1
// baseline (speedup 1.0000x reference)
#include <cuda_runtime.h>

// Capsule routing, fully fused 3-phase pipeline.
// Shapes: B=32, I=1024, O=64, D_in=16, D_out=32.
//
// Pipeline (all deterministic, no atomics):
//   k_uhat  : u_hat[b,i,od] = W[i,od,:]·x[b,i,:]; also per-i-chunk partial
//             sums of u_hat over i (softmax(0) is uniform -> s0 = sum/64).
//   k_squash: reduce 128 chunk partials -> s, (optional bias), squash -> v
//             (or final output).
//   k_route : one streaming pass over u_hat per routing iteration:
//             tile -> SMEM, a = u_hat·v, b_ij update, softmax over O,
//             partial s_next = sum_i c * u_hat  (per chunk).

#define B_   32
#define I_   1024
#define O_   64
#define DN   16
#define DD   32
#define OD   2048      // O_*DD
#define CH   8         // capsules (i) per chunk/tile
#define NCH  128       // I_/CH

// Scratch (static __device__ arrays: allocation-free kernel_launch)
__device__ float g_uhat[(size_t)B_ * I_ * OD];   // 268 MB
__device__ float g_part[(size_t)NCH * B_ * OD];  // 33.5 MB chunk partials
__device__ float g_bij [(size_t)B_ * I_ * O_];   // 8 MB routing logits
__device__ float g_v   [(size_t)B_ * OD];        // v_j

// ---------------------------------------------------------------------------
// K1: u_hat + unweighted per-chunk i-sums.
// grid = (8 od-slices, 128 i-tiles), 256 threads. Thread -> one od column.
// x tile cached in SMEM so W (the 128 MB object) is read exactly once.
// ---------------------------------------------------------------------------
__global__ __launch_bounds__(256) void k_uhat(const float* __restrict__ x,
                                              const float* __restrict__ W) {
    __shared__ float xs[CH][B_][DN];   // 16 KB
    const int od = blockIdx.x * 256 + threadIdx.x;   // 0..2047
    const int i0 = blockIdx.y * CH;

    // cooperative load of x[:, i0:i0+CH, :]
    for (int j = threadIdx.x; j < CH * B_ * DN; j += 256) {
        int b  = j >> 7;          // /(CH*DN)=128
        int il = (j >> 4) & (CH - 1);
        int n  = j & (DN - 1);
        xs[il][b][n] = x[(size_t)b * (I_ * DN) + (i0 + il) * DN + n];
    }
    __syncthreads();

    float acc[B_];
#pragma unroll
    for (int b = 0; b < B_; b++) acc[b] = 0.f;

    for (int il = 0; il < CH; il++) {
        const int i = i0 + il;
        const float4* wr = reinterpret_cast<const float4*>(
            W + ((size_t)i * OD + od) * DN);
        const float4 w0 = wr[0], w1 = wr[1], w2 = wr[2], w3 = wr[3];
        const size_t ub = (size_t)i * OD + od;
#pragma unroll
        for (int b = 0; b < B_; b++) {
            const float4* xb = reinterpret_cast<const float4*>(xs[il][b]);
            const float4 x0 = xb[0], x1 = xb[1], x2 = xb[2], x3 = xb[3];
            float u;
            u  = w0.x * x0.x; u = fmaf(w0.y, x0.y, u);
            u  = fmaf(w0.z, x0.z, u); u = fmaf(w0.w, x0.w, u);
            u  = fmaf(w1.x, x1.x, u); u = fmaf(w1.y, x1.y, u);
            u  = fmaf(w1.z, x1.z, u); u = fmaf(w1.w, x1.w, u);
            u  = fmaf(w2.x, x2.x, u); u = fmaf(w2.y, x2.y, u);
            u  = fmaf(w2.z, x2.z, u); u = fmaf(w2.w, x2.w, u);
            u  = fmaf(w3.x, x3.x, u); u = fmaf(w3.y, x3.y, u);
            u  = fmaf(w3.z, x3.z, u); u = fmaf(w3.w, x3.w, u);
            g_uhat[(size_t)b * (I_ * OD) + ub] = u;
            acc[b] += u;
        }
    }
#pragma unroll
    for (int b = 0; b < B_; b++)
        g_part[((size_t)blockIdx.y * B_ + b) * OD + od] = acc[b];
}

// ---------------------------------------------------------------------------
// K2: chunk-reduce + squash. grid = (16, 32), 128 threads (warp per o).
// out == nullptr -> write g_v; else write final output.
// ---------------------------------------------------------------------------
__global__ __launch_bounds__(128) void k_squash(float factor,
                                                const float* __restrict__ bias,
                                                float* __restrict__ out) {
    const int b = blockIdx.y;
    const int o = blockIdx.x * 4 + (threadIdx.x >> 5);
    const int d = threadIdx.x & 31;

    float s = 0.f;
#pragma unroll 4
    for (int t = 0; t < NCH; t++)
        s += g_part[((size_t)t * B_ + b) * OD + o * DD + d];
    s *= factor;
    if (bias) s += bias[o * DD + d];

    float q = s * s;
#pragma unroll
    for (int sh = 16; sh > 0; sh >>= 1)
        q += __shfl_xor_sync(0xffffffffu, q, sh);

    const float scale = q / (1.f + q) * rsqrtf(q + 1e-8f);
    float* dst = out ? out : g_v;
    dst[((size_t)b * O_ + o) * DD + d] = scale * s;
}

// ---------------------------------------------------------------------------
// K3/K5: one routing iteration pass. grid = (128 chunks, 32 batches),
// 256 threads (8 warps, warp per capsule-in-tile). Dynamic SMEM 77824 B.
// ---------------------------------------------------------------------------
__global__ __launch_bounds__(256) void k_route(int use_bij_in, int write_bij) {
    extern __shared__ float sh[];
    float* tile = sh;                 // CH*OD = 16384 floats (u_hat tile)
    float* sv   = sh + CH * OD;       // 2048 floats (v for this batch)
    float* sa   = sv + OD;            // CH*O_ = 512 (agreements)
    float* sc   = sa + CH * O_;       // CH*O_ = 512 (coupling coeffs)

    const int b  = blockIdx.y;
    const int i0 = blockIdx.x * CH;

    // load u_hat tile (64 KB) + v (8 KB)
    const float4* src = reinterpret_cast<const float4*>(
        g_uhat + ((size_t)b * I_ + i0) * OD);
    float4* dst = reinterpret_cast<float4*>(tile);
#pragma unroll
    for (int k = 0; k < (CH * OD / 4) / 256; k++)
        dst[threadIdx.x + k * 256] = src[threadIdx.x + k * 256];
    for (int k = threadIdx.x; k < OD; k += 256)
        sv[k] = g_v[(size_t)b * OD + k];
    __syncthreads();

    const int wid  = threadIdx.x >> 5;   // capsule within tile
    const int lane = threadIdx.x & 31;   // = d
    const float* trow = tile + wid * OD;

    // agreements a[o] = sum_d u_hat * v (warp butterfly over d)
    for (int o = 0; o < O_; o++) {
        float p = trow[o * DD + lane] * sv[o * DD + lane];
#pragma unroll
        for (int s = 16; s > 0; s >>= 1)
            p += __shfl_xor_sync(0xffffffffu, p, s);
        if (lane == 0) sa[wid * O_ + o] = p;
    }
    __syncwarp();

    // b_ij update + softmax over O (lane holds o=lane and o=lane+32)
    const int i = i0 + wid;
    float a0 = sa[wid * O_ + lane];
    float a1 = sa[wid * O_ + lane + 32];
    if (use_bij_in) {
        a0 += g_bij[((size_t)b * I_ + i) * O_ + lane];
        a1 += g_bij[((size_t)b * I_ + i) * O_ + lane + 32];
    }
    if (write_bij) {
        g_bij[((size_t)b * I_ + i) * O_ + lane]      = a0;
        g_bij[((size_t)b * I_ + i) * O_ + lane + 32] = a1;
    }
    float m = fmaxf(a0, a1);
#pragma unroll
    for (int s = 16; s > 0; s >>= 1)
        m = fmaxf(m, __shfl_xor_sync(0xffffffffu, m, s));
    const float e0 = __expf(a0 - m);
    const float e1 = __expf(a1 - m);
    float es = e0 + e1;
#pragma unroll
    for (int s = 16; s > 0; s >>= 1)
        es += __shfl_xor_sync(0xffffffffu, es, s);
    const float inv = 1.f / es;
    sc[wid * O_ + lane]      = e0 * inv;
    sc[wid * O_ + lane + 32] = e1 * inv;
    __syncthreads();

    // partial s_next[od] = sum_{il} c[il][o] * tile[il][od]
#pragma unroll
    for (int k = 0; k < OD / 256; k++) {
        const int od = threadIdx.x + k * 256;
        const int o  = od >> 5;
        float acc = 0.f;
#pragma unroll
        for (int il = 0; il < CH; il++)
            acc = fmaf(sc[il * O_ + o], tile[il * OD + od], acc);
        g_part[((size_t)blockIdx.x * B_ + b) * OD + od] = acc;
    }
}

// ---------------------------------------------------------------------------
extern "C" void kernel_launch(void* const* d_in, const int* in_sizes, int n_in,
                              void* d_out, int out_size) {
    const float* x    = (const float*)d_in[0];   // [32,1024,16]
    const float* W    = (const float*)d_in[1];   // [1,1024,64,32,16]
    const float* bias = (const float*)d_in[2];   // [1,1,64,32]
    float* out = (float*)d_out;                  // [32,64,32]

    const int route_smem = (CH * OD + OD + 2 * CH * O_) * sizeof(float); // 77824
    cudaFuncSetAttribute(k_route, cudaFuncAttributeMaxDynamicSharedMemorySize,
                         route_smem);

    // it0: u_hat + s0 partials (uniform c = 1/64)
    k_uhat<<<dim3(8, 128), 256>>>(x, W);
    k_squash<<<dim3(16, 32), 128>>>(1.0f / 64.0f, nullptr, nullptr);   // v0
    // it1: a0 -> b_ij, c1 = softmax(a0), s1 partials
    k_route<<<dim3(NCH, B_), 256, route_smem>>>(0, 1);
    k_squash<<<dim3(16, 32), 128>>>(1.0f, nullptr, nullptr);           // v1
    // it2: c2 = softmax(b_ij + a1), s2 partials
    k_route<<<dim3(NCH, B_), 256, route_smem>>>(1, 0);
    k_squash<<<dim3(16, 32), 128>>>(1.0f, bias, out);                  // v2 -> out
}

// round 2
// speedup vs baseline: 1.4763x; 1.4763x over previous
#include <cuda_runtime.h>

// Capsule routing, B=32, I=1024, O=64, D_in=16, D_out=32.
// R1: shuffle-free agreement via XOR-swizzled SMEM tile; MLP-fixed squash;
//     k_uhat split in 2 so ncu (-s 5 -c 1) lands on k_route.

#define B_   32
#define I_   1024
#define O_   64
#define DN   16
#define DD   32
#define OD   2048      // O_*DD
#define OD4  512       // OD/4
#define CH   8         // capsules (i) per chunk/tile
#define NCH  128       // I_/CH

__device__ float g_uhat[(size_t)B_ * I_ * OD];   // 268 MB
__device__ float g_part[(size_t)NCH * B_ * OD];  // 33.5 MB chunk partials
__device__ float g_bij [(size_t)B_ * I_ * O_];   // 8 MB routing logits
__device__ float g_v   [(size_t)B_ * OD];        // v_j

__device__ __forceinline__ int swz(int c) { return c ^ ((c >> 3) & 7); }

// ---------------------------------------------------------------------------
// K1: u_hat + unweighted per-chunk i-sums (softmax(0) uniform -> s0 = sum/64).
// grid = (8 od-slices, 64 i-tiles) x2 launches. Thread -> one od column.
// ---------------------------------------------------------------------------
__global__ __launch_bounds__(256) void k_uhat(const float* __restrict__ x,
                                              const float* __restrict__ W,
                                              int chunk_base) {
    __shared__ float xs[CH][B_][DN];   // 16 KB
    const int od    = blockIdx.x * 256 + threadIdx.x;
    const int chunk = chunk_base + blockIdx.y;
    const int i0    = chunk * CH;

    for (int j = threadIdx.x; j < CH * B_ * DN; j += 256) {
        int b  = j >> 7;
        int il = (j >> 4) & (CH - 1);
        int n  = j & (DN - 1);
        xs[il][b][n] = x[(size_t)b * (I_ * DN) + (i0 + il) * DN + n];
    }
    __syncthreads();

    float acc[B_];
#pragma unroll
    for (int b = 0; b < B_; b++) acc[b] = 0.f;

    for (int il = 0; il < CH; il++) {
        const int i = i0 + il;
        const float4* wr = reinterpret_cast<const float4*>(
            W + ((size_t)i * OD + od) * DN);
        const float4 w0 = wr[0], w1 = wr[1], w2 = wr[2], w3 = wr[3];
        const size_t ub = (size_t)i * OD + od;
#pragma unroll
        for (int b = 0; b < B_; b++) {
            const float4* xb = reinterpret_cast<const float4*>(xs[il][b]);
            const float4 x0 = xb[0], x1 = xb[1], x2 = xb[2], x3 = xb[3];
            float u;
            u  = w0.x * x0.x; u = fmaf(w0.y, x0.y, u);
            u  = fmaf(w0.z, x0.z, u); u = fmaf(w0.w, x0.w, u);
            u  = fmaf(w1.x, x1.x, u); u = fmaf(w1.y, x1.y, u);
            u  = fmaf(w1.z, x1.z, u); u = fmaf(w1.w, x1.w, u);
            u  = fmaf(w2.x, x2.x, u); u = fmaf(w2.y, x2.y, u);
            u  = fmaf(w2.z, x2.z, u); u = fmaf(w2.w, x2.w, u);
            u  = fmaf(w3.x, x3.x, u); u = fmaf(w3.y, x3.y, u);
            u  = fmaf(w3.z, x3.z, u); u = fmaf(w3.w, x3.w, u);
            g_uhat[(size_t)b * (I_ * OD) + ub] = u;
            acc[b] += u;
        }
    }
#pragma unroll
    for (int b = 0; b < B_; b++)
        g_part[((size_t)chunk * B_ + b) * OD + od] = acc[b];
}

// ---------------------------------------------------------------------------
// K2: chunk-reduce + squash. grid = (4, 32), 128 threads.
// lane = o_sub*8 + dg : warp covers 4 o's, 8 float4 d-groups each.
// 4 independent float4 accumulators, fully unrolled -> MLP >= 16.
// ---------------------------------------------------------------------------
__global__ __launch_bounds__(128) void k_squash(float factor,
                                                const float* __restrict__ bias,
                                                float* __restrict__ out) {
    const int b    = blockIdx.y;
    const int w    = threadIdx.x >> 5;
    const int lane = threadIdx.x & 31;
    const int o    = blockIdx.x * 16 + w * 4 + (lane >> 3);
    const int dg   = lane & 7;

    const float4* gp = reinterpret_cast<const float4*>(g_part);
    const size_t base = (size_t)b * OD4 + o * 8 + dg;

    float4 a0 = {0,0,0,0}, a1 = {0,0,0,0}, a2 = {0,0,0,0}, a3 = {0,0,0,0};
#pragma unroll
    for (int t = 0; t < NCH; t += 4) {
        float4 p0 = gp[(size_t)(t + 0) * B_ * OD4 + base];
        float4 p1 = gp[(size_t)(t + 1) * B_ * OD4 + base];
        float4 p2 = gp[(size_t)(t + 2) * B_ * OD4 + base];
        float4 p3 = gp[(size_t)(t + 3) * B_ * OD4 + base];
        a0.x += p0.x; a0.y += p0.y; a0.z += p0.z; a0.w += p0.w;
        a1.x += p1.x; a1.y += p1.y; a1.z += p1.z; a1.w += p1.w;
        a2.x += p2.x; a2.y += p2.y; a2.z += p2.z; a2.w += p2.w;
        a3.x += p3.x; a3.y += p3.y; a3.z += p3.z; a3.w += p3.w;
    }
    float4 s;
    s.x = (a0.x + a1.x + a2.x + a3.x) * factor;
    s.y = (a0.y + a1.y + a2.y + a3.y) * factor;
    s.z = (a0.z + a1.z + a2.z + a3.z) * factor;
    s.w = (a0.w + a1.w + a2.w + a3.w) * factor;
    if (bias) {
        const float4 bb = reinterpret_cast<const float4*>(bias)[o * 8 + dg];
        s.x += bb.x; s.y += bb.y; s.z += bb.z; s.w += bb.w;
    }

    float q = s.x * s.x + s.y * s.y + s.z * s.z + s.w * s.w;
    q += __shfl_xor_sync(0xffffffffu, q, 1);
    q += __shfl_xor_sync(0xffffffffu, q, 2);
    q += __shfl_xor_sync(0xffffffffu, q, 4);

    const float scale = q / (1.f + q) * rsqrtf(q + 1e-8f);
    s.x *= scale; s.y *= scale; s.z *= scale; s.w *= scale;
    float4* dst = reinterpret_cast<float4*>(out ? out : g_v);
    dst[(size_t)b * OD4 + o * 8 + dg] = s;
}

// ---------------------------------------------------------------------------
// K3: one routing pass. grid = (128 chunks, 32 batches), 256 threads.
// Tile + v stored float4-XOR-swizzled: conflict-free for both the linear
// pattern (copy-in / weighted sum) and the per-lane row pattern (agreement).
// Agreement is shuffle-free: lane computes a[o=lane], a[o=lane+32] directly.
// ---------------------------------------------------------------------------
__global__ __launch_bounds__(256) void k_route(int use_bij_in, int write_bij) {
    extern __shared__ float sh[];
    float4* tile4 = reinterpret_cast<float4*>(sh);        // CH*OD4 = 4096
    float4* sv4   = tile4 + CH * OD4;                     // 512
    float*  sc    = reinterpret_cast<float*>(sv4 + OD4);  // CH*O_ = 512 floats

    const int b  = blockIdx.y;
    const int i0 = blockIdx.x * CH;

    // load u_hat tile (64 KB) + v (8 KB), swizzled
    const float4* src = reinterpret_cast<const float4*>(
        g_uhat + ((size_t)b * I_ + i0) * OD);
#pragma unroll
    for (int k = 0; k < (CH * OD4) / 256; k++) {
        const int gq = threadIdx.x + k * 256;
        const int il = gq >> 9, c = gq & (OD4 - 1);
        tile4[il * OD4 + swz(c)] = src[gq];
    }
    const float4* vsrc = reinterpret_cast<const float4*>(g_v + (size_t)b * OD);
#pragma unroll
    for (int k = 0; k < OD4 / 256; k++) {
        const int c = threadIdx.x + k * 256;
        sv4[swz(c)] = vsrc[c];
    }
    __syncthreads();

    const int wid  = threadIdx.x >> 5;   // capsule within tile
    const int lane = threadIdx.x & 31;

    // agreements: a0 for o=lane, a1 for o=lane+32 (no shuffles, no staging)
    float a0 = 0.f, a1 = 0.f;
    {
        const float4* tr = tile4 + wid * OD4;
        const int sx = lane & 7;
#pragma unroll
        for (int dq = 0; dq < 8; dq++) {
            const int c0 = lane * 8 + (dq ^ sx);
            const int c1 = (lane + 32) * 8 + (dq ^ sx);
            const float4 t0 = tr[c0], v0 = sv4[c0];
            const float4 t1 = tr[c1], v1 = sv4[c1];
            a0 = fmaf(t0.x, v0.x, a0); a0 = fmaf(t0.y, v0.y, a0);
            a0 = fmaf(t0.z, v0.z, a0); a0 = fmaf(t0.w, v0.w, a0);
            a1 = fmaf(t1.x, v1.x, a1); a1 = fmaf(t1.y, v1.y, a1);
            a1 = fmaf(t1.z, v1.z, a1); a1 = fmaf(t1.w, v1.w, a1);
        }
    }

    // b_ij update + softmax over O (lane holds o=lane and o=lane+32)
    const int i = i0 + wid;
    if (use_bij_in) {
        a0 += g_bij[((size_t)b * I_ + i) * O_ + lane];
        a1 += g_bij[((size_t)b * I_ + i) * O_ + lane + 32];
    }
    if (write_bij) {
        g_bij[((size_t)b * I_ + i) * O_ + lane]      = a0;
        g_bij[((size_t)b * I_ + i) * O_ + lane + 32] = a1;
    }
    float m = fmaxf(a0, a1);
#pragma unroll
    for (int s = 16; s > 0; s >>= 1)
        m = fmaxf(m, __shfl_xor_sync(0xffffffffu, m, s));
    const float e0 = __expf(a0 - m);
    const float e1 = __expf(a1 - m);
    float es = e0 + e1;
#pragma unroll
    for (int s = 16; s > 0; s >>= 1)
        es += __shfl_xor_sync(0xffffffffu, es, s);
    const float inv = 1.f / es;
    sc[wid * O_ + lane]      = e0 * inv;
    sc[wid * O_ + lane + 32] = e1 * inv;
    __syncthreads();

    // partial s_next = sum_il c[il][o] * tile[il][od], vectorized
    float4* gp = reinterpret_cast<float4*>(g_part);
#pragma unroll
    for (int k = 0; k < OD4 / 256; k++) {
        const int c = threadIdx.x + k * 256;
        const int o = c >> 3;
        const int cs = swz(c);
        float4 acc = {0,0,0,0};
#pragma unroll
        for (int il = 0; il < CH; il++) {
            const float4 t = tile4[il * OD4 + cs];
            const float  s = sc[il * O_ + o];
            acc.x = fmaf(s, t.x, acc.x); acc.y = fmaf(s, t.y, acc.y);
            acc.z = fmaf(s, t.z, acc.z); acc.w = fmaf(s, t.w, acc.w);
        }
        gp[((size_t)blockIdx.x * B_ + b) * OD4 + c] = acc;
    }
}

// ---------------------------------------------------------------------------
extern "C" void kernel_launch(void* const* d_in, const int* in_sizes, int n_in,
                              void* d_out, int out_size) {
    const float* x    = (const float*)d_in[0];   // [32,1024,16]
    const float* W    = (const float*)d_in[1];   // [1,1024,64,32,16]
    const float* bias = (const float*)d_in[2];   // [1,1,64,32]
    float* out = (float*)d_out;                  // [32,64,32]

    const int route_smem = (CH * OD + OD) * sizeof(float) + CH * O_ * sizeof(float);
    cudaFuncSetAttribute(k_route, cudaFuncAttributeMaxDynamicSharedMemorySize,
                         route_smem);

    // launch order keeps k_route at position 6 for ncu (-s 5 -c 1)
    k_uhat<<<dim3(8, 64), 256>>>(x, W, 0);                              // 1
    k_uhat<<<dim3(8, 64), 256>>>(x, W, 64);                             // 2
    k_squash<<<dim3(4, 32), 128>>>(1.0f / 64.0f, nullptr, nullptr);     // 3: v0
    k_route<<<dim3(NCH, B_), 256, route_smem>>>(0, 1);                  // 4
    k_squash<<<dim3(4, 32), 128>>>(1.0f, nullptr, nullptr);             // 5: v1
    k_route<<<dim3(NCH, B_), 256, route_smem>>>(1, 0);                  // 6 (ncu)
    k_squash<<<dim3(4, 32), 128>>>(1.0f, bias, out);                    // 7: out
}

// round 3
// speedup vs baseline: 2.2898x; 1.5511x over previous
#include <cuda_runtime.h>
#include <cuda_fp16.h>

// Capsule routing, B=32, I=1024, O=64, D_in=16, D_out=32.
// R2: u_hat stored fp16 (halves the dominant stream); k_route is fully
//     register-resident (no SMEM tile -> occupancy + MLP); k_uhat does
//     2 od columns/thread with half2 stores.

#define B_   32
#define I_   1024
#define O_   64
#define DN   16
#define DD   32
#define OD   2048      // O_*DD
#define CH   8         // capsules (i) per chunk
#define NCH  128       // I_/CH
#define OD4  512

__device__ __half g_uhat[(size_t)B_ * I_ * OD];  // 134 MB (fp16)
__device__ float  g_part[(size_t)NCH * B_ * OD]; // 33.5 MB chunk partials
__device__ float  g_bij [(size_t)B_ * I_ * O_];  // 8 MB routing logits
__device__ float  g_v   [(size_t)B_ * OD];       // v_j

// ---------------------------------------------------------------------------
// K1: u_hat (fp16) + fp32 per-chunk i-sums (softmax(0) uniform -> s0=sum/64).
// grid = (4 od-slices, 64 chunks) x2 launches; thread -> 2 od columns.
// ---------------------------------------------------------------------------
__global__ __launch_bounds__(256, 2) void k_uhat(const float* __restrict__ x,
                                                 const float* __restrict__ W,
                                                 int chunk_base) {
    __shared__ float xs[CH][B_][DN];   // 16 KB
    const int od0   = (blockIdx.x * 256 + threadIdx.x) * 2;
    const int chunk = chunk_base + blockIdx.y;
    const int i0    = chunk * CH;

    for (int j = threadIdx.x; j < CH * B_ * DN; j += 256) {
        int b  = j >> 7;
        int il = (j >> 4) & (CH - 1);
        int n  = j & (DN - 1);
        xs[il][b][n] = x[(size_t)b * (I_ * DN) + (i0 + il) * DN + n];
    }
    __syncthreads();

    float2 acc[B_];
#pragma unroll
    for (int b = 0; b < B_; b++) acc[b] = make_float2(0.f, 0.f);

    for (int il = 0; il < CH; il++) {
        const int i = i0 + il;
        const float4* wr = reinterpret_cast<const float4*>(
            W + ((size_t)i * OD + od0) * DN);
        const float4 p0 = wr[0], p1 = wr[1], p2 = wr[2], p3 = wr[3];  // row od0
        const float4 q0 = wr[4], q1 = wr[5], q2 = wr[6], q3 = wr[7];  // row od0+1
        __half2* uout = reinterpret_cast<__half2*>(g_uhat) +
                        (((size_t)i * OD + od0) >> 1);
#pragma unroll
        for (int b = 0; b < B_; b++) {
            const float4* xb = reinterpret_cast<const float4*>(xs[il][b]);
            const float4 x0 = xb[0], x1 = xb[1], x2 = xb[2], x3 = xb[3];
            float u0, u1;
            u0  = p0.x * x0.x;        u0 = fmaf(p0.y, x0.y, u0);
            u0  = fmaf(p0.z, x0.z, u0); u0 = fmaf(p0.w, x0.w, u0);
            u0  = fmaf(p1.x, x1.x, u0); u0 = fmaf(p1.y, x1.y, u0);
            u0  = fmaf(p1.z, x1.z, u0); u0 = fmaf(p1.w, x1.w, u0);
            u0  = fmaf(p2.x, x2.x, u0); u0 = fmaf(p2.y, x2.y, u0);
            u0  = fmaf(p2.z, x2.z, u0); u0 = fmaf(p2.w, x2.w, u0);
            u0  = fmaf(p3.x, x3.x, u0); u0 = fmaf(p3.y, x3.y, u0);
            u0  = fmaf(p3.z, x3.z, u0); u0 = fmaf(p3.w, x3.w, u0);
            u1  = q0.x * x0.x;        u1 = fmaf(q0.y, x0.y, u1);
            u1  = fmaf(q0.z, x0.z, u1); u1 = fmaf(q0.w, x0.w, u1);
            u1  = fmaf(q1.x, x1.x, u1); u1 = fmaf(q1.y, x1.y, u1);
            u1  = fmaf(q1.z, x1.z, u1); u1 = fmaf(q1.w, x1.w, u1);
            u1  = fmaf(q2.x, x2.x, u1); u1 = fmaf(q2.y, x2.y, u1);
            u1  = fmaf(q2.z, x2.z, u1); u1 = fmaf(q2.w, x2.w, u1);
            u1  = fmaf(q3.x, x3.x, u1); u1 = fmaf(q3.y, x3.y, u1);
            u1  = fmaf(q3.z, x3.z, u1); u1 = fmaf(q3.w, x3.w, u1);
            uout[(size_t)b * (I_ * OD / 2)] = __floats2half2_rn(u0, u1);
            acc[b].x += u0; acc[b].y += u1;
        }
    }
#pragma unroll
    for (int b = 0; b < B_; b++)
        *reinterpret_cast<float2*>(
            g_part + ((size_t)chunk * B_ + b) * OD + od0) = acc[b];
}

// ---------------------------------------------------------------------------
// K2: chunk-reduce + squash (fp32 partials). grid = (4, 32), 128 threads.
// ---------------------------------------------------------------------------
__global__ __launch_bounds__(128) void k_squash(float factor,
                                                const float* __restrict__ bias,
                                                float* __restrict__ out) {
    const int b    = blockIdx.y;
    const int w    = threadIdx.x >> 5;
    const int lane = threadIdx.x & 31;
    const int o    = blockIdx.x * 16 + w * 4 + (lane >> 3);
    const int dg   = lane & 7;

    const float4* gp = reinterpret_cast<const float4*>(g_part);
    const size_t base = (size_t)b * OD4 + o * 8 + dg;

    float4 a0 = {0,0,0,0}, a1 = {0,0,0,0}, a2 = {0,0,0,0}, a3 = {0,0,0,0};
#pragma unroll
    for (int t = 0; t < NCH; t += 4) {
        float4 p0 = gp[(size_t)(t + 0) * B_ * OD4 + base];
        float4 p1 = gp[(size_t)(t + 1) * B_ * OD4 + base];
        float4 p2 = gp[(size_t)(t + 2) * B_ * OD4 + base];
        float4 p3 = gp[(size_t)(t + 3) * B_ * OD4 + base];
        a0.x += p0.x; a0.y += p0.y; a0.z += p0.z; a0.w += p0.w;
        a1.x += p1.x; a1.y += p1.y; a1.z += p1.z; a1.w += p1.w;
        a2.x += p2.x; a2.y += p2.y; a2.z += p2.z; a2.w += p2.w;
        a3.x += p3.x; a3.y += p3.y; a3.z += p3.z; a3.w += p3.w;
    }
    float4 s;
    s.x = (a0.x + a1.x + a2.x + a3.x) * factor;
    s.y = (a0.y + a1.y + a2.y + a3.y) * factor;
    s.z = (a0.z + a1.z + a2.z + a3.z) * factor;
    s.w = (a0.w + a1.w + a2.w + a3.w) * factor;
    if (bias) {
        const float4 bb = reinterpret_cast<const float4*>(bias)[o * 8 + dg];
        s.x += bb.x; s.y += bb.y; s.z += bb.z; s.w += bb.w;
    }

    float q = s.x * s.x + s.y * s.y + s.z * s.z + s.w * s.w;
    q += __shfl_xor_sync(0xffffffffu, q, 1);
    q += __shfl_xor_sync(0xffffffffu, q, 2);
    q += __shfl_xor_sync(0xffffffffu, q, 4);

    const float scale = q / (1.f + q) * rsqrtf(q + 1e-8f);
    s.x *= scale; s.y *= scale; s.z *= scale; s.w *= scale;
    float4* dst = reinterpret_cast<float4*>(out ? out : g_v);
    dst[(size_t)b * OD4 + o * 8 + dg] = s;
}

// ---------------------------------------------------------------------------
// K3: one routing pass, register-resident. grid = (128 chunks, 32 batches),
// 256 threads. Thread t owns od column [8t, 8t+8) (one uint4 of halfs) for
// all CH capsules: agreement = quad shuffle reduce; weighted sum reuses the
// same registers. SMEM = 4 KB (sa + sc only).
// ---------------------------------------------------------------------------
__global__ __launch_bounds__(256) void k_route(int use_bij_in, int write_bij) {
    __shared__ float sa[CH][O_];
    __shared__ float sc[CH][O_];

    const int b  = blockIdx.y;
    const int i0 = blockIdx.x * CH;
    const int t  = threadIdx.x;
    const int o  = t >> 2;          // output capsule owned by this quad

    // load u_hat columns: CH independent LDG.128
    const uint4* usrc = reinterpret_cast<const uint4*>(
        g_uhat + ((size_t)b * I_ + i0) * OD) + t;
    uint4 u[CH];
#pragma unroll
    for (int il = 0; il < CH; il++) u[il] = usrc[il * 256];

    // v segment for this column (8 floats)
    const float4* vsrc = reinterpret_cast<const float4*>(g_v + (size_t)b * OD) + t * 2;
    const float4 v0 = vsrc[0], v1 = vsrc[1];

    // agreement: a[il][o] partial over this thread's 8 d's, quad-reduced
#pragma unroll
    for (int il = 0; il < CH; il++) {
        const __half2* h = reinterpret_cast<const __half2*>(&u[il]);
        float2 f0 = __half22float2(h[0]), f1 = __half22float2(h[1]);
        float2 f2 = __half22float2(h[2]), f3 = __half22float2(h[3]);
        float a;
        a  = f0.x * v0.x;        a = fmaf(f0.y, v0.y, a);
        a  = fmaf(f1.x, v0.z, a); a = fmaf(f1.y, v0.w, a);
        a  = fmaf(f2.x, v1.x, a); a = fmaf(f2.y, v1.y, a);
        a  = fmaf(f3.x, v1.z, a); a = fmaf(f3.y, v1.w, a);
        a += __shfl_xor_sync(0xffffffffu, a, 1);
        a += __shfl_xor_sync(0xffffffffu, a, 2);
        if ((t & 3) == 0) sa[il][o] = a;
    }
    __syncthreads();

    // softmax over O: warp wid -> capsule wid, lane holds o=lane, o=lane+32
    {
        const int wid  = t >> 5;
        const int lane = t & 31;
        const int i = i0 + wid;
        float a0 = sa[wid][lane];
        float a1 = sa[wid][lane + 32];
        if (use_bij_in) {
            a0 += g_bij[((size_t)b * I_ + i) * O_ + lane];
            a1 += g_bij[((size_t)b * I_ + i) * O_ + lane + 32];
        }
        if (write_bij) {
            g_bij[((size_t)b * I_ + i) * O_ + lane]      = a0;
            g_bij[((size_t)b * I_ + i) * O_ + lane + 32] = a1;
        }
        float m = fmaxf(a0, a1);
#pragma unroll
        for (int s = 16; s > 0; s >>= 1)
            m = fmaxf(m, __shfl_xor_sync(0xffffffffu, m, s));
        const float e0 = __expf(a0 - m);
        const float e1 = __expf(a1 - m);
        float es = e0 + e1;
#pragma unroll
        for (int s = 16; s > 0; s >>= 1)
            es += __shfl_xor_sync(0xffffffffu, es, s);
        const float inv = 1.f / es;
        sc[wid][lane]      = e0 * inv;
        sc[wid][lane + 32] = e1 * inv;
    }
    __syncthreads();

    // weighted sum: s_next[od] partial = sum_il c[il][o] * u[il][od]
    float4 r0 = {0,0,0,0}, r1 = {0,0,0,0};
#pragma unroll
    for (int il = 0; il < CH; il++) {
        const float s = sc[il][o];
        const __half2* h = reinterpret_cast<const __half2*>(&u[il]);
        float2 f0 = __half22float2(h[0]), f1 = __half22float2(h[1]);
        float2 f2 = __half22float2(h[2]), f3 = __half22float2(h[3]);
        r0.x = fmaf(s, f0.x, r0.x); r0.y = fmaf(s, f0.y, r0.y);
        r0.z = fmaf(s, f1.x, r0.z); r0.w = fmaf(s, f1.y, r0.w);
        r1.x = fmaf(s, f2.x, r1.x); r1.y = fmaf(s, f2.y, r1.y);
        r1.z = fmaf(s, f3.x, r1.z); r1.w = fmaf(s, f3.y, r1.w);
    }
    float4* gp = reinterpret_cast<float4*>(
        g_part + ((size_t)blockIdx.x * B_ + b) * OD) + t * 2;
    gp[0] = r0;
    gp[1] = r1;
}

// ---------------------------------------------------------------------------
extern "C" void kernel_launch(void* const* d_in, const int* in_sizes, int n_in,
                              void* d_out, int out_size) {
    const float* x    = (const float*)d_in[0];   // [32,1024,16]
    const float* W    = (const float*)d_in[1];   // [1,1024,64,32,16]
    const float* bias = (const float*)d_in[2];   // [1,1,64,32]
    float* out = (float*)d_out;                  // [32,64,32]

    k_uhat<<<dim3(4, 64), 256>>>(x, W, 0);                           // 1
    k_uhat<<<dim3(4, 64), 256>>>(x, W, 64);                          // 2
    k_squash<<<dim3(4, 32), 128>>>(1.0f / 64.0f, nullptr, nullptr);  // 3: v0
    k_route<<<dim3(NCH, B_), 256>>>(0, 1);                           // 4
    k_squash<<<dim3(4, 32), 128>>>(1.0f, nullptr, nullptr);          // 5: v1
    k_route<<<dim3(NCH, B_), 256>>>(1, 0);                           // 6 (ncu)
    k_squash<<<dim3(4, 32), 128>>>(1.0f, bias, out);                 // 7: out
}

// round 4
// speedup vs baseline: 2.9415x; 1.2846x over previous
#include <cuda_runtime.h>
#include <cuda_fp16.h>

// Capsule routing, B=32, I=1024, O=64, D_in=16, D_out=32.
// R3: k_uhat uses packed fp32x2 FMA (fma.rn.f32x2, k-paired so W/x float4
//     loads ARE the packed operands, zero pack overhead) and drops the
//     partial-sum path (registers freed -> occupancy). s0 comes from a new
//     streaming k_sum0. k_route covers 4 chunks/block (double-buffered) so
//     g_part shrinks 33.5 -> 8.4 MB.

#define B_   32
#define I_   1024
#define O_   64
#define DN   16
#define DD   32
#define OD   2048      // O_*DD
#define CH   8         // capsules (i) per chunk
#define G_   4         // chunks per route block
#define NG   32        // I_/(CH*G_) partial groups
#define OD4  512

__device__ __half g_uhat[(size_t)B_ * I_ * OD];  // 134 MB (fp16)
__device__ float  g_part[(size_t)NG * B_ * OD];  // 8.4 MB group partials
__device__ float  g_bij [(size_t)B_ * I_ * O_];  // 8 MB routing logits
__device__ float  g_v   [(size_t)B_ * OD];       // v_j

#define FFMA2(d, a, b, c) \
    asm("fma.rn.f32x2 %0, %1, %2, %3;" : "=l"(d) : "l"(a), "l"(b), "l"(c))
#define MUL2(d, a, b) \
    asm("mul.rn.f32x2 %0, %1, %2;" : "=l"(d) : "l"(a), "l"(b))
#define PACK2(d, lo, hi) \
    asm("mov.b64 %0, {%1, %2};" : "=l"(d) : "f"(lo), "f"(hi))
#define UNPACK2(lo, hi, v) \
    asm("mov.b64 {%0, %1}, %2;" : "=f"(lo), "=f"(hi) : "l"(v))

// ---------------------------------------------------------------------------
// K1: u_hat (fp16). grid = (2 od-slices, 128 chunks), 256 threads.
// Thread owns 4 od rows; k paired into f32x2 lanes (even/odd partial sums).
// ---------------------------------------------------------------------------
__global__ __launch_bounds__(256, 2) void k_uhat(const float* __restrict__ x,
                                                 const float* __restrict__ W) {
    __shared__ float xs[CH][B_][DN];   // 16 KB
    const int od0 = blockIdx.x * 1024 + threadIdx.x * 4;
    const int i0  = blockIdx.y * CH;

    for (int j = threadIdx.x; j < CH * B_ * DN; j += 256) {
        int b  = j >> 7;
        int il = (j >> 4) & (CH - 1);
        int n  = j & (DN - 1);
        xs[il][b][n] = x[(size_t)b * (I_ * DN) + (i0 + il) * DN + n];
    }
    __syncthreads();

#pragma unroll 1
    for (int il = 0; il < CH; il++) {
        const int i = i0 + il;
        // W rows od0..od0+3 : 64 consecutive floats = 32 f32x2 pairs
        const float4* wr = reinterpret_cast<const float4*>(
            W + ((size_t)i * OD + od0) * DN);
        unsigned long long wp[32];          // [od][kpair] : od*8 + kp
#pragma unroll
        for (int r = 0; r < 16; r++) {
            const float4 f = wr[r];
            PACK2(wp[r * 2 + 0], f.x, f.y);
            PACK2(wp[r * 2 + 1], f.z, f.w);
        }
        __half* ubase = g_uhat + (size_t)i * OD + od0;

#pragma unroll 4
        for (int b = 0; b < B_; b++) {
            const float4* xb = reinterpret_cast<const float4*>(xs[il][b]);
            const float4 x0 = xb[0], x1 = xb[1], x2 = xb[2], x3 = xb[3];
            unsigned long long xp[8];
            PACK2(xp[0], x0.x, x0.y); PACK2(xp[1], x0.z, x0.w);
            PACK2(xp[2], x1.x, x1.y); PACK2(xp[3], x1.z, x1.w);
            PACK2(xp[4], x2.x, x2.y); PACK2(xp[5], x2.z, x2.w);
            PACK2(xp[6], x3.x, x3.y); PACK2(xp[7], x3.z, x3.w);

            unsigned long long acc[4];
#pragma unroll
            for (int od = 0; od < 4; od++) MUL2(acc[od], wp[od * 8], xp[0]);
#pragma unroll
            for (int kp = 1; kp < 8; kp++)
#pragma unroll
                for (int od = 0; od < 4; od++)
                    FFMA2(acc[od], wp[od * 8 + kp], xp[kp], acc[od]);

            float u[4];
#pragma unroll
            for (int od = 0; od < 4; od++) {
                float lo, hi;
                UNPACK2(lo, hi, acc[od]);
                u[od] = lo + hi;
            }
            const __half2 h01 = __floats2half2_rn(u[0], u[1]);
            const __half2 h23 = __floats2half2_rn(u[2], u[3]);
            uint2 st;
            st.x = *reinterpret_cast<const unsigned*>(&h01);
            st.y = *reinterpret_cast<const unsigned*>(&h23);
            *reinterpret_cast<uint2*>(ubase + (size_t)b * (I_ * OD)) = st;
        }
    }
}

// ---------------------------------------------------------------------------
// K1b: s0 partials = unweighted i-sums of u_hat (softmax(0) is uniform).
// grid = (NG, 32), 256 threads; thread owns 8 ods, sums 32 i's.
// ---------------------------------------------------------------------------
__global__ __launch_bounds__(256) void k_sum0() {
    const int b = blockIdx.y;
    const int i0 = blockIdx.x * (CH * G_);
    const uint4* src = reinterpret_cast<const uint4*>(
        g_uhat + ((size_t)b * I_ + i0) * OD) + threadIdx.x;

    float4 r0 = {0,0,0,0}, r1 = {0,0,0,0};
#pragma unroll
    for (int il = 0; il < CH * G_; il++) {
        const uint4 u = src[il * 256];
        const __half2* h = reinterpret_cast<const __half2*>(&u);
        const float2 f0 = __half22float2(h[0]), f1 = __half22float2(h[1]);
        const float2 f2 = __half22float2(h[2]), f3 = __half22float2(h[3]);
        r0.x += f0.x; r0.y += f0.y; r0.z += f1.x; r0.w += f1.y;
        r1.x += f2.x; r1.y += f2.y; r1.z += f3.x; r1.w += f3.y;
    }
    float4* gp = reinterpret_cast<float4*>(
        g_part + ((size_t)blockIdx.x * B_ + b) * OD) + threadIdx.x * 2;
    gp[0] = r0;
    gp[1] = r1;
}

// ---------------------------------------------------------------------------
// K2: group-reduce + squash. grid = (4, 32), 128 threads.
// ---------------------------------------------------------------------------
__global__ __launch_bounds__(128) void k_squash(float factor,
                                                const float* __restrict__ bias,
                                                float* __restrict__ out) {
    const int b    = blockIdx.y;
    const int w    = threadIdx.x >> 5;
    const int lane = threadIdx.x & 31;
    const int o    = blockIdx.x * 16 + w * 4 + (lane >> 3);
    const int dg   = lane & 7;

    const float4* gp = reinterpret_cast<const float4*>(g_part);
    const size_t base = (size_t)b * OD4 + o * 8 + dg;

    float4 a0 = {0,0,0,0}, a1 = {0,0,0,0}, a2 = {0,0,0,0}, a3 = {0,0,0,0};
#pragma unroll
    for (int t = 0; t < NG; t += 4) {
        float4 p0 = gp[(size_t)(t + 0) * B_ * OD4 + base];
        float4 p1 = gp[(size_t)(t + 1) * B_ * OD4 + base];
        float4 p2 = gp[(size_t)(t + 2) * B_ * OD4 + base];
        float4 p3 = gp[(size_t)(t + 3) * B_ * OD4 + base];
        a0.x += p0.x; a0.y += p0.y; a0.z += p0.z; a0.w += p0.w;
        a1.x += p1.x; a1.y += p1.y; a1.z += p1.z; a1.w += p1.w;
        a2.x += p2.x; a2.y += p2.y; a2.z += p2.z; a2.w += p2.w;
        a3.x += p3.x; a3.y += p3.y; a3.z += p3.z; a3.w += p3.w;
    }
    float4 s;
    s.x = (a0.x + a1.x + a2.x + a3.x) * factor;
    s.y = (a0.y + a1.y + a2.y + a3.y) * factor;
    s.z = (a0.z + a1.z + a2.z + a3.z) * factor;
    s.w = (a0.w + a1.w + a2.w + a3.w) * factor;
    if (bias) {
        const float4 bb = reinterpret_cast<const float4*>(bias)[o * 8 + dg];
        s.x += bb.x; s.y += bb.y; s.z += bb.z; s.w += bb.w;
    }

    float q = s.x * s.x + s.y * s.y + s.z * s.z + s.w * s.w;
    q += __shfl_xor_sync(0xffffffffu, q, 1);
    q += __shfl_xor_sync(0xffffffffu, q, 2);
    q += __shfl_xor_sync(0xffffffffu, q, 4);

    const float scale = q / (1.f + q) * rsqrtf(q + 1e-8f);
    s.x *= scale; s.y *= scale; s.z *= scale; s.w *= scale;
    float4* dst = reinterpret_cast<float4*>(out ? out : g_v);
    dst[(size_t)b * OD4 + o * 8 + dg] = s;
}

// ---------------------------------------------------------------------------
// K3: one routing pass, register-resident, G_ chunks per block with
// double-buffered u loads. grid = (NG, 32), 256 threads.
// ---------------------------------------------------------------------------
__global__ __launch_bounds__(256, 2) void k_route(int use_bij_in, int write_bij) {
    __shared__ float sa[CH][O_];
    __shared__ float sc[CH][O_];

    const int b  = blockIdx.y;
    const int t  = threadIdx.x;
    const int o  = t >> 2;
    const int ibase = blockIdx.x * (CH * G_);

    const float4* vsrc =
        reinterpret_cast<const float4*>(g_v + (size_t)b * OD) + t * 2;
    const float4 v0 = vsrc[0], v1 = vsrc[1];

    const uint4* usrc = reinterpret_cast<const uint4*>(
        g_uhat + ((size_t)b * I_ + ibase) * OD) + t;

    uint4 ua[CH], ub[CH];
#pragma unroll
    for (int il = 0; il < CH; il++) ua[il] = usrc[il * 256];

    float4 r0 = {0,0,0,0}, r1 = {0,0,0,0};

#pragma unroll
    for (int g = 0; g < G_; g++) {
        uint4* ucur = (g & 1) ? ub : ua;
        uint4* unxt = (g & 1) ? ua : ub;
        if (g < G_ - 1) {
#pragma unroll
            for (int il = 0; il < CH; il++)
                unxt[il] = usrc[(g + 1) * CH * 256 + il * 256];
        }
        const int i0 = ibase + g * CH;

        // agreement: quad-reduced dot with v
#pragma unroll
        for (int il = 0; il < CH; il++) {
            const __half2* h = reinterpret_cast<const __half2*>(&ucur[il]);
            const float2 f0 = __half22float2(h[0]), f1 = __half22float2(h[1]);
            const float2 f2 = __half22float2(h[2]), f3 = __half22float2(h[3]);
            float a;
            a  = f0.x * v0.x;         a = fmaf(f0.y, v0.y, a);
            a  = fmaf(f1.x, v0.z, a); a = fmaf(f1.y, v0.w, a);
            a  = fmaf(f2.x, v1.x, a); a = fmaf(f2.y, v1.y, a);
            a  = fmaf(f3.x, v1.z, a); a = fmaf(f3.y, v1.w, a);
            a += __shfl_xor_sync(0xffffffffu, a, 1);
            a += __shfl_xor_sync(0xffffffffu, a, 2);
            if ((t & 3) == 0) sa[il][o] = a;
        }
        __syncthreads();

        // softmax over O: warp wid -> capsule wid
        {
            const int wid  = t >> 5;
            const int lane = t & 31;
            const int i = i0 + wid;
            float a0 = sa[wid][lane];
            float a1 = sa[wid][lane + 32];
            if (use_bij_in) {
                a0 += g_bij[((size_t)b * I_ + i) * O_ + lane];
                a1 += g_bij[((size_t)b * I_ + i) * O_ + lane + 32];
            }
            if (write_bij) {
                g_bij[((size_t)b * I_ + i) * O_ + lane]      = a0;
                g_bij[((size_t)b * I_ + i) * O_ + lane + 32] = a1;
            }
            float m = fmaxf(a0, a1);
#pragma unroll
            for (int s = 16; s > 0; s >>= 1)
                m = fmaxf(m, __shfl_xor_sync(0xffffffffu, m, s));
            const float e0 = __expf(a0 - m);
            const float e1 = __expf(a1 - m);
            float es = e0 + e1;
#pragma unroll
            for (int s = 16; s > 0; s >>= 1)
                es += __shfl_xor_sync(0xffffffffu, es, s);
            const float inv = 1.f / es;
            sc[wid][lane]      = e0 * inv;
            sc[wid][lane + 32] = e1 * inv;
        }
        __syncthreads();

        // weighted sum accumulate
#pragma unroll
        for (int il = 0; il < CH; il++) {
            const float s = sc[il][o];
            const __half2* h = reinterpret_cast<const __half2*>(&ucur[il]);
            const float2 f0 = __half22float2(h[0]), f1 = __half22float2(h[1]);
            const float2 f2 = __half22float2(h[2]), f3 = __half22float2(h[3]);
            r0.x = fmaf(s, f0.x, r0.x); r0.y = fmaf(s, f0.y, r0.y);
            r0.z = fmaf(s, f1.x, r0.z); r0.w = fmaf(s, f1.y, r0.w);
            r1.x = fmaf(s, f2.x, r1.x); r1.y = fmaf(s, f2.y, r1.y);
            r1.z = fmaf(s, f3.x, r1.z); r1.w = fmaf(s, f3.y, r1.w);
        }
    }

    float4* gp = reinterpret_cast<float4*>(
        g_part + ((size_t)blockIdx.x * B_ + b) * OD) + t * 2;
    gp[0] = r0;
    gp[1] = r1;
}

// ---------------------------------------------------------------------------
extern "C" void kernel_launch(void* const* d_in, const int* in_sizes, int n_in,
                              void* d_out, int out_size) {
    const float* x    = (const float*)d_in[0];   // [32,1024,16]
    const float* W    = (const float*)d_in[1];   // [1,1024,64,32,16]
    const float* bias = (const float*)d_in[2];   // [1,1,64,32]
    float* out = (float*)d_out;                  // [32,64,32]

    k_uhat<<<dim3(2, 128), 256>>>(x, W);                             // 1
    k_sum0<<<dim3(NG, B_), 256>>>();                                 // 2
    k_squash<<<dim3(4, 32), 128>>>(1.0f / 64.0f, nullptr, nullptr);  // 3: v0
    k_route<<<dim3(NG, B_), 256>>>(0, 1);                            // 4
    k_squash<<<dim3(4, 32), 128>>>(1.0f, nullptr, nullptr);          // 5: v1
    k_route<<<dim3(NG, B_), 256>>>(1, 0);                            // 6 (ncu)
    k_squash<<<dim3(4, 32), 128>>>(1.0f, bias, out);                 // 7: out
}